// round 8
// baseline (speedup 1.0000x reference)
#include <cuda_runtime.h>
#include <cstdint>

#define HW     65536
#define BHW    131072
#define WDIM   1024
#define HDIM   64

// ---------------- global scratch ----------------
// g_acc: [0]=N1 (masked (p,k) count)  [1]=N0 (mp0 count)
// [2..5] Sum pn_a   [6..15] Sum pn_a*pn_b (a<=b: 00,01,02,03,11,12,13,22,23,33)
// [16..23] SG2  [24..31] QG2
// [32..159] interleaved: [32+2c]=SA_c [33+2c]=QA_c
__device__ float g_acc[160];
__device__ float g_wts[9 * BHW];    // softmax weights (full), plane-major
__device__ float g_wtsg[9 * BHW];   // msel-masked softmax weights
__device__ float g_vv[72 * BHW];    // pre-BN2 g values, plane-major [k*8+j]

#define PACK2(dst, f) asm("mov.b64 %0, {%1, %1};" : "=l"(dst) : "r"(__float_as_uint(f)))
#define FMA2(acc, a, b) asm("fma.rn.f32x2 %0, %1, %2, %0;" : "+l"(acc) : "l"(a), "l"(b))

__device__ __forceinline__ uint32_t smem_u32(const void* p) {
    uint32_t a;
    asm("{ .reg .u64 t; cvta.to.shared.u64 t, %1; cvt.u32.u64 %0, t; }" : "=r"(a) : "l"(p));
    return a;
}

// ---------------- block reduction -> atomicAdd into g_acc ----------------
template <int NV, int NW>
__device__ __forceinline__ void block_reduce_atomic(const float* vals, float* red, int tid, int accBase) {
    int lane = tid & 31, w = tid >> 5;
#pragma unroll
    for (int v = 0; v < NV; v++) {
        float r = vals[v];
#pragma unroll
        for (int o = 16; o; o >>= 1) r += __shfl_down_sync(0xffffffffu, r, o);
        if (lane == 0) red[v * NW + w] = r;
    }
    __syncthreads();
    if (tid < NV) {
        float r = 0.f;
#pragma unroll
        for (int ww = 0; ww < NW; ww++) r += red[tid * NW + ww];
        atomicAdd(&g_acc[accBase + tid], r);
    }
}

// first-layer BN affine from pn moments: var(w.pn) = w^T Cov w
__device__ __forceinline__ void affine_from_moments(const float* wrow, float gam, float bet,
                                                    float& a_out, float& b_out) {
    float n = fmaxf(g_acc[0], 1.f);
    const int qi[4][4] = {{0,1,2,3},{1,4,5,6},{2,5,7,8},{3,6,8,9}};
    float e2 = 0.f, mean = 0.f;
#pragma unroll
    for (int a = 0; a < 4; a++) {
        float wa = wrow[a];
        mean += wa * (g_acc[2 + a] / n);
        float row = 0.f;
#pragma unroll
        for (int bb = 0; bb < 4; bb++) row += wrow[bb] * (g_acc[6 + qi[a][bb]] / n);
        e2 += wa * row;
    }
    float var = e2 - mean * mean;
    float a_ = gam * rsqrtf(var + 1e-5f);
    a_out = a_;
    b_out = bet - mean * a_;
}

// ---------------- K0 ----------------
__global__ void k0_zero() {
    int t = threadIdx.x;
    if (t < 160) g_acc[t] = 0.f;
}

// ---------------- K1: pn moment stats + mask counts (tiled) ----------------
__global__ void k1_stats(const float* __restrict__ x, const float* __restrict__ mask) {
    __shared__ float tile[5 * 3 * 260];
    __shared__ float red[16 * 8];
    int tid = threadIdx.x;

    int base = blockIdx.x * 256;
    int b = base >> 16, p0 = base & (HW - 1);
    int y = p0 >> 10, x0 = p0 & (WDIM - 1);
    const float* xb0 = x + (size_t)b * 68 * HW;
    const float* mb = mask + (size_t)b * HW;

    for (int f = tid; f < 5 * 3 * 260; f += 256) {
        int pl = f / 780, rem = f - pl * 780;
        int r = rem / 260, cx = rem - r * 260;
        float v = 0.f;
        if (cx < 258) {
            int gy = y - 1 + r, gx = x0 - 1 + cx;
            if (gy >= 0 && gy < HDIM && gx >= 0 && gx < WDIM) {
                int gp = gy * WDIM + gx;
                v = (pl == 0) ? mb[gp] : xb0[(size_t)(pl - 1) * HW + gp];
            }
        }
        tile[f] = v;
    }
    __syncthreads();

    int cc = tid + 1;
    float c0 = tile[780 + 260 + cc], c1 = tile[2 * 780 + 260 + cc];
    float c2 = tile[3 * 780 + 260 + cc], c3 = tile[4 * 780 + 260 + cc];
    float cnt1 = 0.f, cnt0 = (tile[260 + cc] > 0.f) ? 1.f : 0.f;
    float s[4] = {0.f, 0.f, 0.f, 0.f};
    float q[10];
#pragma unroll
    for (int j = 0; j < 10; j++) q[j] = 0.f;

#pragma unroll
    for (int k = 0; k < 9; k++) {
        int r = k / 3, dx = k % 3 - 1;
        int tix = r * 260 + cc + dx;
        if (!(tile[tix] > 0.f)) continue;
        cnt1 += 1.f;
        float pn0 = tile[780 + tix] - c0, pn1 = tile[2 * 780 + tix] - c1;
        float pn2 = tile[3 * 780 + tix] - c2, pn3 = tile[4 * 780 + tix] - c3;
        s[0] += pn0; s[1] += pn1; s[2] += pn2; s[3] += pn3;
        q[0] += pn0 * pn0; q[1] += pn0 * pn1; q[2] += pn0 * pn2; q[3] += pn0 * pn3;
        q[4] += pn1 * pn1; q[5] += pn1 * pn2; q[6] += pn1 * pn3;
        q[7] += pn2 * pn2; q[8] += pn2 * pn3; q[9] += pn3 * pn3;
    }

    float vals[16];
    vals[0] = cnt1; vals[1] = cnt0;
#pragma unroll
    for (int a = 0; a < 4; a++) vals[2 + a] = s[a];
#pragma unroll
    for (int j = 0; j < 10; j++) vals[6 + j] = q[j];
    block_reduce_atomic<16, 8>(vals, red, tid, 0);
}

// ---------------- K2: softmax weights + vv planes + gbn2 stats ----------------
__global__ void k2_wts(const float* __restrict__ x, const float* __restrict__ mask,
                       const float* __restrict__ w1, const float* __restrict__ bn1_g,
                       const float* __restrict__ bn1_b, const float* __restrict__ w2,
                       const float* __restrict__ b2, const float* __restrict__ g1,
                       const float* __restrict__ gbn1_g, const float* __restrict__ gbn1_b,
                       const float* __restrict__ g2) {
    __shared__ float tile[5 * 3 * 260];
    __shared__ float w1s[32], g1s[32], g2s[64], w2s[8], abp[32], b2sh[1];
    __shared__ float red[16 * 8];
    int tid = threadIdx.x;
    if (tid < 32) { w1s[tid] = w1[tid]; g1s[tid] = g1[tid]; }
    if (tid < 64) g2s[tid] = g2[tid];
    if (tid < 8)  w2s[tid] = w2[tid];
    if (tid == 0) b2sh[0] = b2[0];
    if (tid >= 64 && tid < 80) {
        int t2 = tid - 64;
        int path = t2 >> 3, j = t2 & 7;
        const float* wrow = (path ? g1 : w1) + j * 4;
        float gam = path ? gbn1_g[j] : bn1_g[j];
        float bet = path ? gbn1_b[j] : bn1_b[j];
        float a_, b_;
        affine_from_moments(wrow, gam, bet, a_, b_);
        abp[path * 16 + j] = a_;
        abp[path * 16 + 8 + j] = b_;
    }

    int base = blockIdx.x * 256;
    int b = base >> 16, p0 = base & (HW - 1);
    int y = p0 >> 10, x0 = p0 & (WDIM - 1);
    const float* xb0 = x + (size_t)b * 68 * HW;
    const float* mb = mask + (size_t)b * HW;

    for (int f = tid; f < 5 * 3 * 260; f += 256) {
        int pl = f / 780, rem = f - pl * 780;
        int r = rem / 260, cx = rem - r * 260;
        float v = 0.f;
        if (cx < 258) {
            int gy = y - 1 + r, gx = x0 - 1 + cx;
            if (gy >= 0 && gy < HDIM && gx >= 0 && gx < WDIM) {
                int gp = gy * WDIM + gx;
                v = (pl == 0) ? mb[gp] : xb0[(size_t)(pl - 1) * HW + gp];
            }
        }
        tile[f] = v;
    }
    __syncthreads();

    int i = base + tid;
    int cc = tid + 1;
    float c0 = tile[780 + 260 + cc], c1 = tile[2 * 780 + 260 + cc];
    float c2 = tile[3 * 780 + 260 + cc], c3 = tile[4 * 780 + 260 + cc];
    float logit[9];
    float sg2[8], qg2[8];
#pragma unroll
    for (int j = 0; j < 8; j++) { sg2[j] = qg2[j] = 0.f; }
    unsigned mbits = 0;

#pragma unroll
    for (int k = 0; k < 9; k++) {
        int r = k / 3, dx = k % 3 - 1;
        int tix = r * 260 + cc + dx;
        float lg = 0.f;
        if (tile[tix] > 0.f) {
            mbits |= 1u << k;
            float pn0 = tile[780 + tix] - c0, pn1 = tile[2 * 780 + tix] - c1;
            float pn2 = tile[3 * 780 + tix] - c2, pn3 = tile[4 * 780 + tix] - c3;
            float u[8];
            float l = b2sh[0];
#pragma unroll
            for (int j = 0; j < 8; j++) {
                float h = pn0 * w1s[j * 4] + pn1 * w1s[j * 4 + 1] + pn2 * w1s[j * 4 + 2] + pn3 * w1s[j * 4 + 3];
                float hn = fmaxf(h * abp[j] + abp[8 + j], 0.f);
                l += hn * w2s[j];
                float qv = pn0 * g1s[j * 4] + pn1 * g1s[j * 4 + 1] + pn2 * g1s[j * 4 + 2] + pn3 * g1s[j * 4 + 3];
                u[j] = fmaxf(qv * abp[16 + j] + abp[24 + j], 0.f);
            }
            lg = l;
#pragma unroll
            for (int j = 0; j < 8; j++) {
                float vv = 0.f;
#pragma unroll
                for (int m = 0; m < 8; m++) vv += u[m] * g2s[j * 8 + m];
                g_vv[(size_t)(k * 8 + j) * BHW + i] = vv;
                sg2[j] += vv; qg2[j] += vv * vv;
            }
        } else {
#pragma unroll
            for (int j = 0; j < 8; j++) g_vv[(size_t)(k * 8 + j) * BHW + i] = 0.f;
        }
        logit[k] = lg;
    }

    float mx = logit[0];
#pragma unroll
    for (int k = 1; k < 9; k++) mx = fmaxf(mx, logit[k]);
    float s = 0.f, e[9];
#pragma unroll
    for (int k = 0; k < 9; k++) { e[k] = __expf(logit[k] - mx); s += e[k]; }
    float inv = 1.f / s;
#pragma unroll
    for (int k = 0; k < 9; k++) {
        float wk = e[k] * inv;
        g_wts[(size_t)k * BHW + i] = wk;
        g_wtsg[(size_t)k * BHW + i] = ((mbits >> k) & 1u) ? wk : 0.f;
    }

    float vals[16];
#pragma unroll
    for (int j = 0; j < 8; j++) { vals[j] = sg2[j]; vals[8 + j] = qg2[j]; }
    block_reduce_atomic<16, 8>(vals, red, tid, 16);
}

// ---------------- K3: fused producer+GEMM with cp.async double-buffered staging ----------------
// dynamic smem (floats):
//   wTs   [0, 8704)    transposed weights [136][64]
//   stg0  [8704, 15040)   staging A (fagg: [8][3][264], g: [9][256])
//   stg1  [15040, 21376)  staging B
//   smf0  [21376, 23424)  feats chunk A [8][256]
//   smf1  [23424, 25472)  feats chunk B
#define K3_STG0  8704
#define K3_STG1  15040
#define K3_SMF0  21376
#define K3_SMF1  23424
#define K3_SMEMF 25472

__device__ __forceinline__ void k3_issue_fagg(uint32_t stg, const float* __restrict__ xpl,
                                              int y, int x0, int tid) {
#pragma unroll
    for (int q = 0; q < 6; q++) {
        int s = q * 256 + tid;              // 0..1535
        int j = s / 192;
        int rem = s - j * 192;
        int r = rem >> 6, c4 = rem & 63;
        int gy = y - 1 + r;
        int ok = (gy >= 0 && gy < HDIM) ? 16 : 0;
        int gyc = min(max(gy, 0), HDIM - 1);
        const float* src = xpl + (size_t)j * HW + gyc * WDIM + x0 + 4 * c4;
        uint32_t dst = stg + (uint32_t)(j * 792 + r * 264 + 4 + 4 * c4) * 4u;
        asm volatile("cp.async.cg.shared.global [%0], [%1], 16, %2;" :: "r"(dst), "l"(src), "r"(ok) : "memory");
    }
    if (tid < 48) {
        int j = tid / 6, rem = tid % 6;
        int r = rem >> 1, side = rem & 1;
        int gy = y - 1 + r;
        int gx = side ? x0 + 256 : x0 - 1;
        int ok = (gy >= 0 && gy < HDIM && gx >= 0 && gx < WDIM) ? 4 : 0;
        int gyc = min(max(gy, 0), HDIM - 1);
        int gxc = min(max(gx, 0), WDIM - 1);
        const float* src = xpl + (size_t)j * HW + gyc * WDIM + gxc;
        uint32_t dst = stg + (uint32_t)(j * 792 + r * 264 + (side ? 260 : 3)) * 4u;
        asm volatile("cp.async.ca.shared.global [%0], [%1], 4, %2;" :: "r"(dst), "l"(src), "r"(ok) : "memory");
    }
}

__device__ __forceinline__ void k3_issue_g(uint32_t stg, const float* __restrict__ vvb,
                                           const float* __restrict__ wgb, int tid) {
#pragma unroll
    for (int q = 0; q < 2; q++) {
        int s = q * 256 + tid;              // 0..511
        int j = s >> 6, c4 = s & 63;
        const float* src = vvb + (size_t)j * BHW + 4 * c4;
        uint32_t dst = stg + (uint32_t)(j * 256 + 4 * c4) * 4u;
        asm volatile("cp.async.cg.shared.global [%0], [%1], 16;" :: "r"(dst), "l"(src) : "memory");
    }
    if (tid < 64) {
        const float* src = wgb + 4 * tid;
        uint32_t dst = stg + (uint32_t)(8 * 256 + 4 * tid) * 4u;
        asm volatile("cp.async.cg.shared.global [%0], [%1], 16;" :: "r"(dst), "l"(src) : "memory");
    }
}

__global__ void __launch_bounds__(256, 2) k3_gemm(const float* __restrict__ x,
                                                  const float* __restrict__ mask,
                                                  const float* __restrict__ w_agg,
                                                  const float* __restrict__ gbn2_g,
                                                  const float* __restrict__ gbn2_b,
                                                  float* __restrict__ out) {
    extern __shared__ float sm[];
    float* wTs = sm;
    __shared__ float a2s[8], b2s[8];
    int tid = threadIdx.x;
    uint32_t smb = smem_u32(sm);
    uint32_t stgu0 = smb + K3_STG0 * 4u, stgu1 = smb + K3_STG1 * 4u;

    for (int e = tid; e < 64 * 136; e += 256) {
        float v = w_agg[e];
        int o = e / 136, ii = e - o * 136;
        wTs[ii * 64 + o] = v;
    }
    if (tid < 8) {
        float n = fmaxf(g_acc[0], 1.f);
        float mean2 = g_acc[16 + tid] / n;
        float var2  = g_acc[24 + tid] / n - mean2 * mean2;
        float a2 = gbn2_g[tid] * rsqrtf(var2 + 1e-5f);
        a2s[tid] = a2;
        b2s[tid] = gbn2_b[tid] - mean2 * a2;
    }

    int base = blockIdx.x * 256;
    int b = base >> 16, p0 = base & (HW - 1);
    int y = p0 >> 10, x0 = p0 & (WDIM - 1);
    const float* xb4 = x + (size_t)b * 68 * HW + (size_t)4 * HW;

    float wv[9];
#pragma unroll
    for (int k = 0; k < 9; k++) wv[k] = g_wts[(size_t)k * BHW + base + tid];

    // prologue: issue chunk 0 (fagg channels 0..7)
    k3_issue_fagg(stgu0, xb4, y, x0, tid);
    asm volatile("cp.async.commit_group;" ::: "memory");

    // GEMM tiling: 4 px x 16 ch per thread; weights consumed as packed ch-pairs.
    int pg = tid & 63, cg = tid >> 6;
    unsigned long long acc[32];   // acc[px*8 + cp]: f32x2 over (ch = cg*16 + 2cp, +1)
#pragma unroll
    for (int t = 0; t < 32; t++) acc[t] = 0ULL;

    for (int c = 0; c < 17; c++) {
        if (c < 16) {
            int cn = c + 1;
            if (cn < 8) {
                k3_issue_fagg(cn & 1 ? stgu1 : stgu0, xb4 + (size_t)(8 * cn) * HW, y, x0, tid);
            } else {
                int k = cn - 8;
                k3_issue_g(cn & 1 ? stgu1 : stgu0,
                           g_vv + (size_t)(k * 8) * BHW + base,
                           g_wtsg + (size_t)k * BHW + base, tid);
            }
            asm volatile("cp.async.commit_group;" ::: "memory");
            asm volatile("cp.async.wait_group 1;" ::: "memory");
        } else {
            asm volatile("cp.async.wait_group 0;" ::: "memory");
        }
        __syncthreads();   // chunk c's staging fully visible

        float* stg = sm + ((c & 1) ? K3_STG1 : K3_STG0);
        float* smf = sm + ((c & 1) ? K3_SMF1 : K3_SMF0);
        if (c < 8) {
#pragma unroll
            for (int j = 0; j < 8; j++) {
                const float* xj = stg + j * 792 + tid;
                float fc = wv[0] * xj[3]       + wv[1] * xj[4]       + wv[2] * xj[5];
                fc      += wv[3] * xj[264 + 3] + wv[4] * xj[264 + 4] + wv[5] * xj[264 + 5];
                fc      += wv[6] * xj[528 + 3] + wv[7] * xj[528 + 4] + wv[8] * xj[528 + 5];
                smf[j * 256 + tid] = fc;
            }
        } else {
            float wg = stg[2048 + tid];
#pragma unroll
            for (int j = 0; j < 8; j++) {
                smf[j * 256 + tid] = fmaxf(stg[j * 256 + tid] * a2s[j] + b2s[j], 0.f) * wg;
            }
        }
        __syncthreads();   // smf ready

        // GEMM over this chunk: f per-lane (4 px, dup to f32x2), w broadcast packed pairs
#pragma unroll
        for (int kk = 0; kk < 8; kk++) {
            float4 f = *reinterpret_cast<const float4*>(smf + kk * 256 + pg * 4);
            unsigned long long fd0, fd1, fd2, fd3;
            PACK2(fd0, f.x); PACK2(fd1, f.y); PACK2(fd2, f.z); PACK2(fd3, f.w);
            const float* wr = wTs + (c * 8 + kk) * 64 + cg * 16;
            ulonglong2 wp0 = *reinterpret_cast<const ulonglong2*>(wr);
            ulonglong2 wp1 = *reinterpret_cast<const ulonglong2*>(wr + 4);
            ulonglong2 wp2 = *reinterpret_cast<const ulonglong2*>(wr + 8);
            ulonglong2 wp3 = *reinterpret_cast<const ulonglong2*>(wr + 12);
            unsigned long long wp[8] = {wp0.x, wp0.y, wp1.x, wp1.y, wp2.x, wp2.y, wp3.x, wp3.y};
#pragma unroll
            for (int cp = 0; cp < 8; cp++) {
                FMA2(acc[0 * 8 + cp], fd0, wp[cp]);
                FMA2(acc[1 * 8 + cp], fd1, wp[cp]);
                FMA2(acc[2 * 8 + cp], fd2, wp[cp]);
                FMA2(acc[3 * 8 + cp], fd3, wp[cp]);
            }
        }
    }

    // ---- epilogue: store raw out + abn stats ----
    const float* mp = mask + (size_t)b * HW + p0 + pg * 4;
    float4 mk = *reinterpret_cast<const float4*>(mp);
    float mm[4] = { mk.x > 0.f ? 1.f : 0.f, mk.y > 0.f ? 1.f : 0.f,
                    mk.z > 0.f ? 1.f : 0.f, mk.w > 0.f ? 1.f : 0.f };

    float* ob = out + (size_t)b * 64 * HW + p0 + pg * 4;
    int lane = tid & 31;
#pragma unroll
    for (int cp = 0; cp < 8; cp++) {
        float lo0 = __uint_as_float((unsigned)acc[0 * 8 + cp]);
        float hi0 = __uint_as_float((unsigned)(acc[0 * 8 + cp] >> 32));
        float lo1 = __uint_as_float((unsigned)acc[1 * 8 + cp]);
        float hi1 = __uint_as_float((unsigned)(acc[1 * 8 + cp] >> 32));
        float lo2 = __uint_as_float((unsigned)acc[2 * 8 + cp]);
        float hi2 = __uint_as_float((unsigned)(acc[2 * 8 + cp] >> 32));
        float lo3 = __uint_as_float((unsigned)acc[3 * 8 + cp]);
        float hi3 = __uint_as_float((unsigned)(acc[3 * 8 + cp] >> 32));
        int chE = cg * 16 + 2 * cp;
        float4 vE = make_float4(lo0, lo1, lo2, lo3);
        float4 vO = make_float4(hi0, hi1, hi2, hi3);
        *reinterpret_cast<float4*>(ob + (size_t)chE * HW) = vE;
        *reinterpret_cast<float4*>(ob + (size_t)(chE + 1) * HW) = vO;

        float svE = lo0 * mm[0] + lo1 * mm[1] + lo2 * mm[2] + lo3 * mm[3];
        float qE  = lo0 * lo0 * mm[0] + lo1 * lo1 * mm[1] + lo2 * lo2 * mm[2] + lo3 * lo3 * mm[3];
        float svO = hi0 * mm[0] + hi1 * mm[1] + hi2 * mm[2] + hi3 * mm[3];
        float qO  = hi0 * hi0 * mm[0] + hi1 * hi1 * mm[1] + hi2 * hi2 * mm[2] + hi3 * hi3 * mm[3];
#pragma unroll
        for (int o2 = 16; o2; o2 >>= 1) {
            svE += __shfl_down_sync(0xffffffffu, svE, o2);
            qE  += __shfl_down_sync(0xffffffffu, qE, o2);
            svO += __shfl_down_sync(0xffffffffu, svO, o2);
            qO  += __shfl_down_sync(0xffffffffu, qO, o2);
        }
        if (lane == 0) {
            atomicAdd(&g_acc[32 + 2 * chE], svE);
            atomicAdd(&g_acc[33 + 2 * chE], qE);
            atomicAdd(&g_acc[32 + 2 * (chE + 1)], svO);
            atomicAdd(&g_acc[33 + 2 * (chE + 1)], qO);
        }
    }
}

// ---------------- K4: abn normalize + relu + mask ----------------
__global__ void k4_final(float* __restrict__ out, const float* __restrict__ mask,
                         const float* __restrict__ abn_g, const float* __restrict__ abn_b) {
    int t = blockIdx.x * 256 + threadIdx.x;
    int e = t * 4;
    int b = e >> 22;
    int c = (e >> 16) & 63;
    int p = e & (HW - 1);
    float n0   = fmaxf(g_acc[1], 1.f);
    float mean = g_acc[32 + 2 * c] / n0;
    float var  = g_acc[33 + 2 * c] / n0 - mean * mean;
    float a    = abn_g[c] * rsqrtf(var + 1e-5f);
    float bb   = abn_b[c] - mean * a;
    float4 v  = reinterpret_cast<float4*>(out)[t];
    float4 mk = *reinterpret_cast<const float4*>(mask + (size_t)b * HW + p);
    v.x = (mk.x > 0.f) ? fmaxf(v.x * a + bb, 0.f) : 0.f;
    v.y = (mk.y > 0.f) ? fmaxf(v.y * a + bb, 0.f) : 0.f;
    v.z = (mk.z > 0.f) ? fmaxf(v.z * a + bb, 0.f) : 0.f;
    v.w = (mk.w > 0.f) ? fmaxf(v.w * a + bb, 0.f) : 0.f;
    reinterpret_cast<float4*>(out)[t] = v;
}

// ---------------- host launcher ----------------
extern "C" void kernel_launch(void* const* d_in, const int* in_sizes, int n_in,
                              void* d_out, int out_size) {
    const float* x      = (const float*)d_in[0];
    const float* mask   = (const float*)d_in[1];
    const float* w1     = (const float*)d_in[2];
    const float* bn1_g  = (const float*)d_in[3];
    const float* bn1_b  = (const float*)d_in[4];
    const float* w2     = (const float*)d_in[5];
    const float* b2     = (const float*)d_in[6];
    const float* g1     = (const float*)d_in[7];
    const float* gbn1_g = (const float*)d_in[8];
    const float* gbn1_b = (const float*)d_in[9];
    const float* g2     = (const float*)d_in[10];
    const float* gbn2_g = (const float*)d_in[11];
    const float* gbn2_b = (const float*)d_in[12];
    const float* w_agg  = (const float*)d_in[13];
    const float* abn_g  = (const float*)d_in[14];
    const float* abn_b  = (const float*)d_in[15];
    float* out = (float*)d_out;

    cudaFuncSetAttribute(k3_gemm, cudaFuncAttributeMaxDynamicSharedMemorySize, K3_SMEMF * 4);

    k0_zero<<<1, 256>>>();
    k1_stats<<<BHW / 256, 256>>>(x, mask);
    k2_wts<<<BHW / 256, 256>>>(x, mask, w1, bn1_g, bn1_b, w2, b2, g1, gbn1_g, gbn1_b, g2);
    k3_gemm<<<BHW / 256, 256, K3_SMEMF * 4>>>(x, mask, w_agg, gbn2_g, gbn2_b, out);
    k4_final<<<(2 * 64 * HW / 4) / 256, 256>>>(out, mask, abn_g, abn_b);
}

// round 9
// speedup vs baseline: 1.0300x; 1.0300x over previous
#include <cuda_runtime.h>
#include <cstdint>

#define HW     65536
#define BHW    131072
#define WDIM   1024
#define HDIM   64

// ---------------- global scratch ----------------
// g_acc: [0]=N1 (masked (p,k) count)  [1]=N0 (mp0 count)
// [2..5] Sum pn_a   [6..15] Sum pn_a*pn_b (a<=b: 00,01,02,03,11,12,13,22,23,33)
// [16..23] SG2  [24..31] QG2
// [32..159] interleaved: [32+2c]=SA_c [33+2c]=QA_c
__device__ float g_acc[160];
__device__ float g_wts[9 * BHW];    // softmax weights (full), plane-major
__device__ float g_wtsg[9 * BHW];   // msel-masked softmax weights
__device__ float g_vv[72 * BHW];    // pre-BN2 g values, plane-major [k*8+j]

#define PACK2(dst, f) asm("mov.b64 %0, {%1, %1};" : "=l"(dst) : "r"(__float_as_uint(f)))
#define FMA2(acc, a, b) asm("fma.rn.f32x2 %0, %1, %2, %0;" : "+l"(acc) : "l"(a), "l"(b))

__device__ __forceinline__ uint32_t smem_u32(const void* p) {
    uint32_t a;
    asm("{ .reg .u64 t; cvta.to.shared.u64 t, %1; cvt.u32.u64 %0, t; }" : "=r"(a) : "l"(p));
    return a;
}

// ---------------- block reduction -> atomicAdd into g_acc ----------------
template <int NV, int NW>
__device__ __forceinline__ void block_reduce_atomic(const float* vals, float* red, int tid, int accBase) {
    int lane = tid & 31, w = tid >> 5;
#pragma unroll
    for (int v = 0; v < NV; v++) {
        float r = vals[v];
#pragma unroll
        for (int o = 16; o; o >>= 1) r += __shfl_down_sync(0xffffffffu, r, o);
        if (lane == 0) red[v * NW + w] = r;
    }
    __syncthreads();
    if (tid < NV) {
        float r = 0.f;
#pragma unroll
        for (int ww = 0; ww < NW; ww++) r += red[tid * NW + ww];
        atomicAdd(&g_acc[accBase + tid], r);
    }
}

// first-layer BN affine from pn moments: var(w.pn) = w^T Cov w
__device__ __forceinline__ void affine_from_moments(const float* wrow, float gam, float bet,
                                                    float& a_out, float& b_out) {
    float n = fmaxf(g_acc[0], 1.f);
    const int qi[4][4] = {{0,1,2,3},{1,4,5,6},{2,5,7,8},{3,6,8,9}};
    float e2 = 0.f, mean = 0.f;
#pragma unroll
    for (int a = 0; a < 4; a++) {
        float wa = wrow[a];
        mean += wa * (g_acc[2 + a] / n);
        float row = 0.f;
#pragma unroll
        for (int bb = 0; bb < 4; bb++) row += wrow[bb] * (g_acc[6 + qi[a][bb]] / n);
        e2 += wa * row;
    }
    float var = e2 - mean * mean;
    float a_ = gam * rsqrtf(var + 1e-5f);
    a_out = a_;
    b_out = bet - mean * a_;
}

// ---------------- K0 ----------------
__global__ void k0_zero() {
    int t = threadIdx.x;
    if (t < 160) g_acc[t] = 0.f;
}

// ---------------- K1: pn moment stats + mask counts (tiled) ----------------
__global__ void k1_stats(const float* __restrict__ x, const float* __restrict__ mask) {
    __shared__ float tile[5 * 3 * 260];
    __shared__ float red[16 * 8];
    int tid = threadIdx.x;

    int base = blockIdx.x * 256;
    int b = base >> 16, p0 = base & (HW - 1);
    int y = p0 >> 10, x0 = p0 & (WDIM - 1);
    const float* xb0 = x + (size_t)b * 68 * HW;
    const float* mb = mask + (size_t)b * HW;

    for (int f = tid; f < 5 * 3 * 260; f += 256) {
        int pl = f / 780, rem = f - pl * 780;
        int r = rem / 260, cx = rem - r * 260;
        float v = 0.f;
        if (cx < 258) {
            int gy = y - 1 + r, gx = x0 - 1 + cx;
            if (gy >= 0 && gy < HDIM && gx >= 0 && gx < WDIM) {
                int gp = gy * WDIM + gx;
                v = (pl == 0) ? mb[gp] : xb0[(size_t)(pl - 1) * HW + gp];
            }
        }
        tile[f] = v;
    }
    __syncthreads();

    int cc = tid + 1;
    float c0 = tile[780 + 260 + cc], c1 = tile[2 * 780 + 260 + cc];
    float c2 = tile[3 * 780 + 260 + cc], c3 = tile[4 * 780 + 260 + cc];
    float cnt1 = 0.f, cnt0 = (tile[260 + cc] > 0.f) ? 1.f : 0.f;
    float s[4] = {0.f, 0.f, 0.f, 0.f};
    float q[10];
#pragma unroll
    for (int j = 0; j < 10; j++) q[j] = 0.f;

#pragma unroll
    for (int k = 0; k < 9; k++) {
        int r = k / 3, dx = k % 3 - 1;
        int tix = r * 260 + cc + dx;
        if (!(tile[tix] > 0.f)) continue;
        cnt1 += 1.f;
        float pn0 = tile[780 + tix] - c0, pn1 = tile[2 * 780 + tix] - c1;
        float pn2 = tile[3 * 780 + tix] - c2, pn3 = tile[4 * 780 + tix] - c3;
        s[0] += pn0; s[1] += pn1; s[2] += pn2; s[3] += pn3;
        q[0] += pn0 * pn0; q[1] += pn0 * pn1; q[2] += pn0 * pn2; q[3] += pn0 * pn3;
        q[4] += pn1 * pn1; q[5] += pn1 * pn2; q[6] += pn1 * pn3;
        q[7] += pn2 * pn2; q[8] += pn2 * pn3; q[9] += pn3 * pn3;
    }

    float vals[16];
    vals[0] = cnt1; vals[1] = cnt0;
#pragma unroll
    for (int a = 0; a < 4; a++) vals[2 + a] = s[a];
#pragma unroll
    for (int j = 0; j < 10; j++) vals[6 + j] = q[j];
    block_reduce_atomic<16, 8>(vals, red, tid, 0);
}

// ---------------- K2: softmax weights + vv planes + gbn2 stats ----------------
__global__ void k2_wts(const float* __restrict__ x, const float* __restrict__ mask,
                       const float* __restrict__ w1, const float* __restrict__ bn1_g,
                       const float* __restrict__ bn1_b, const float* __restrict__ w2,
                       const float* __restrict__ b2, const float* __restrict__ g1,
                       const float* __restrict__ gbn1_g, const float* __restrict__ gbn1_b,
                       const float* __restrict__ g2) {
    __shared__ float tile[5 * 3 * 260];
    __shared__ float w1s[32], g1s[32], g2s[64], w2s[8], abp[32], b2sh[1];
    __shared__ float red[16 * 8];
    int tid = threadIdx.x;
    if (tid < 32) { w1s[tid] = w1[tid]; g1s[tid] = g1[tid]; }
    if (tid < 64) g2s[tid] = g2[tid];
    if (tid < 8)  w2s[tid] = w2[tid];
    if (tid == 0) b2sh[0] = b2[0];
    if (tid >= 64 && tid < 80) {
        int t2 = tid - 64;
        int path = t2 >> 3, j = t2 & 7;
        const float* wrow = (path ? g1 : w1) + j * 4;
        float gam = path ? gbn1_g[j] : bn1_g[j];
        float bet = path ? gbn1_b[j] : bn1_b[j];
        float a_, b_;
        affine_from_moments(wrow, gam, bet, a_, b_);
        abp[path * 16 + j] = a_;
        abp[path * 16 + 8 + j] = b_;
    }

    int base = blockIdx.x * 256;
    int b = base >> 16, p0 = base & (HW - 1);
    int y = p0 >> 10, x0 = p0 & (WDIM - 1);
    const float* xb0 = x + (size_t)b * 68 * HW;
    const float* mb = mask + (size_t)b * HW;

    for (int f = tid; f < 5 * 3 * 260; f += 256) {
        int pl = f / 780, rem = f - pl * 780;
        int r = rem / 260, cx = rem - r * 260;
        float v = 0.f;
        if (cx < 258) {
            int gy = y - 1 + r, gx = x0 - 1 + cx;
            if (gy >= 0 && gy < HDIM && gx >= 0 && gx < WDIM) {
                int gp = gy * WDIM + gx;
                v = (pl == 0) ? mb[gp] : xb0[(size_t)(pl - 1) * HW + gp];
            }
        }
        tile[f] = v;
    }
    __syncthreads();

    int i = base + tid;
    int cc = tid + 1;
    float c0 = tile[780 + 260 + cc], c1 = tile[2 * 780 + 260 + cc];
    float c2 = tile[3 * 780 + 260 + cc], c3 = tile[4 * 780 + 260 + cc];
    float logit[9];
    float sg2[8], qg2[8];
#pragma unroll
    for (int j = 0; j < 8; j++) { sg2[j] = qg2[j] = 0.f; }
    unsigned mbits = 0;

#pragma unroll
    for (int k = 0; k < 9; k++) {
        int r = k / 3, dx = k % 3 - 1;
        int tix = r * 260 + cc + dx;
        float lg = 0.f;
        if (tile[tix] > 0.f) {
            mbits |= 1u << k;
            float pn0 = tile[780 + tix] - c0, pn1 = tile[2 * 780 + tix] - c1;
            float pn2 = tile[3 * 780 + tix] - c2, pn3 = tile[4 * 780 + tix] - c3;
            float u[8];
            float l = b2sh[0];
#pragma unroll
            for (int j = 0; j < 8; j++) {
                float h = pn0 * w1s[j * 4] + pn1 * w1s[j * 4 + 1] + pn2 * w1s[j * 4 + 2] + pn3 * w1s[j * 4 + 3];
                float hn = fmaxf(h * abp[j] + abp[8 + j], 0.f);
                l += hn * w2s[j];
                float qv = pn0 * g1s[j * 4] + pn1 * g1s[j * 4 + 1] + pn2 * g1s[j * 4 + 2] + pn3 * g1s[j * 4 + 3];
                u[j] = fmaxf(qv * abp[16 + j] + abp[24 + j], 0.f);
            }
            lg = l;
#pragma unroll
            for (int j = 0; j < 8; j++) {
                float vv = 0.f;
#pragma unroll
                for (int m = 0; m < 8; m++) vv += u[m] * g2s[j * 8 + m];
                g_vv[(size_t)(k * 8 + j) * BHW + i] = vv;
                sg2[j] += vv; qg2[j] += vv * vv;
            }
        } else {
#pragma unroll
            for (int j = 0; j < 8; j++) g_vv[(size_t)(k * 8 + j) * BHW + i] = 0.f;
        }
        logit[k] = lg;
    }

    float mx = logit[0];
#pragma unroll
    for (int k = 1; k < 9; k++) mx = fmaxf(mx, logit[k]);
    float s = 0.f, e[9];
#pragma unroll
    for (int k = 0; k < 9; k++) { e[k] = __expf(logit[k] - mx); s += e[k]; }
    float inv = 1.f / s;
#pragma unroll
    for (int k = 0; k < 9; k++) {
        float wk = e[k] * inv;
        g_wts[(size_t)k * BHW + i] = wk;
        g_wtsg[(size_t)k * BHW + i] = ((mbits >> k) & 1u) ? wk : 0.f;
    }

    float vals[16];
#pragma unroll
    for (int j = 0; j < 8; j++) { vals[j] = sg2[j]; vals[8 + j] = qg2[j]; }
    block_reduce_atomic<16, 8>(vals, red, tid, 16);
}

// ---------------- K3: fused producer+GEMM, 128-px tiles, 3 blocks/SM ----------------
// dynamic smem (floats):
//   wTs   [0, 8704)        transposed weights [136][64]
//   stg0  [8704, 11968)    staging A (fagg: [8][3][136]=3264; g: [8][128]+wg[128]=1152)
//   stg1  [11968, 15232)   staging B
//   smf0  [15232, 16256)   feats chunk A [8][128]
//   smf1  [16256, 17280)   feats chunk B
#define K3_STG0  8704
#define K3_STG1  11968
#define K3_SMF0  15232
#define K3_SMF1  16256
#define K3_SMEMF 17280

// fagg staging row layout: float idx 3..132 hold cols x0-1 .. x0+128 (per plane j, row r)
__device__ __forceinline__ void k3_issue_fagg(uint32_t stg, const float* __restrict__ xpl,
                                              int y, int x0, int tid) {
#pragma unroll
    for (int q = 0; q < 3; q++) {
        int s = q * 256 + tid;              // 0..767
        int j = s / 96;
        int rem = s - j * 96;
        int r = rem >> 5, c4 = rem & 31;
        int gy = y - 1 + r;
        int ok = (gy >= 0 && gy < HDIM) ? 16 : 0;
        int gyc = min(max(gy, 0), HDIM - 1);
        const float* src = xpl + (size_t)j * HW + gyc * WDIM + x0 + 4 * c4;
        uint32_t dst = stg + (uint32_t)(j * 408 + r * 136 + 4 + 4 * c4) * 4u;
        asm volatile("cp.async.cg.shared.global [%0], [%1], 16, %2;" :: "r"(dst), "l"(src), "r"(ok) : "memory");
    }
    if (tid < 48) {
        int j = tid / 6, rem = tid % 6;
        int r = rem >> 1, side = rem & 1;
        int gy = y - 1 + r;
        int gx = side ? x0 + 128 : x0 - 1;
        int ok = (gy >= 0 && gy < HDIM && gx >= 0 && gx < WDIM) ? 4 : 0;
        int gyc = min(max(gy, 0), HDIM - 1);
        int gxc = min(max(gx, 0), WDIM - 1);
        const float* src = xpl + (size_t)j * HW + gyc * WDIM + gxc;
        uint32_t dst = stg + (uint32_t)(j * 408 + r * 136 + (side ? 132 : 3)) * 4u;
        asm volatile("cp.async.ca.shared.global [%0], [%1], 4, %2;" :: "r"(dst), "l"(src), "r"(ok) : "memory");
    }
}

__device__ __forceinline__ void k3_issue_g(uint32_t stg, const float* __restrict__ vvb,
                                           const float* __restrict__ wgb, int tid) {
    {   // vv: [8][128] = 256 x 16B
        int j = tid >> 5, c4 = tid & 31;
        const float* src = vvb + (size_t)j * BHW + 4 * c4;
        uint32_t dst = stg + (uint32_t)(j * 128 + 4 * c4) * 4u;
        asm volatile("cp.async.cg.shared.global [%0], [%1], 16;" :: "r"(dst), "l"(src) : "memory");
    }
    if (tid < 32) {   // wg: 128 floats = 32 x 16B
        const float* src = wgb + 4 * tid;
        uint32_t dst = stg + (uint32_t)(1024 + 4 * tid) * 4u;
        asm volatile("cp.async.cg.shared.global [%0], [%1], 16;" :: "r"(dst), "l"(src) : "memory");
    }
}

__global__ void __launch_bounds__(256, 3) k3_gemm(const float* __restrict__ x,
                                                  const float* __restrict__ mask,
                                                  const float* __restrict__ w_agg,
                                                  const float* __restrict__ gbn2_g,
                                                  const float* __restrict__ gbn2_b,
                                                  float* __restrict__ out) {
    extern __shared__ float sm[];
    float* wTs = sm;
    __shared__ float a2s[8], b2s[8];
    int tid = threadIdx.x;
    uint32_t smb = smem_u32(sm);
    uint32_t stgu0 = smb + K3_STG0 * 4u, stgu1 = smb + K3_STG1 * 4u;

    for (int e = tid; e < 64 * 136; e += 256) {
        float v = w_agg[e];
        int o = e / 136, ii = e - o * 136;
        wTs[ii * 64 + o] = v;
    }
    if (tid < 8) {
        float n = fmaxf(g_acc[0], 1.f);
        float mean2 = g_acc[16 + tid] / n;
        float var2  = g_acc[24 + tid] / n - mean2 * mean2;
        float a2 = gbn2_g[tid] * rsqrtf(var2 + 1e-5f);
        a2s[tid] = a2;
        b2s[tid] = gbn2_b[tid] - mean2 * a2;
    }

    int base = blockIdx.x * 128;
    int b = base >> 16, p0 = base & (HW - 1);
    int y = p0 >> 10, x0 = p0 & (WDIM - 1);
    const float* xb4 = x + (size_t)b * 68 * HW + (size_t)4 * HW;

    int px = tid & 127, jj = tid >> 7;     // transform mapping: 2 threads per px
    float wv[9];
#pragma unroll
    for (int k = 0; k < 9; k++) wv[k] = g_wts[(size_t)k * BHW + base + px];

    // prologue: issue chunk 0 (fagg channels 0..7)
    k3_issue_fagg(stgu0, xb4, y, x0, tid);
    asm volatile("cp.async.commit_group;" ::: "memory");

    // GEMM tiling: 4 px x 8 ch per thread (pg 0..31 -> px pg*4; cg 0..7 -> ch cg*8)
    int pg = tid & 31, cg = tid >> 5;
    unsigned long long acc[16];   // acc[px4*4 + cp]
#pragma unroll
    for (int t = 0; t < 16; t++) acc[t] = 0ULL;

    for (int c = 0; c < 17; c++) {
        if (c < 16) {
            int cn = c + 1;
            if (cn < 8) {
                k3_issue_fagg(cn & 1 ? stgu1 : stgu0, xb4 + (size_t)(8 * cn) * HW, y, x0, tid);
            } else {
                int k = cn - 8;
                k3_issue_g(cn & 1 ? stgu1 : stgu0,
                           g_vv + (size_t)(k * 8) * BHW + base,
                           g_wtsg + (size_t)k * BHW + base, tid);
            }
            asm volatile("cp.async.commit_group;" ::: "memory");
            asm volatile("cp.async.wait_group 1;" ::: "memory");
        } else {
            asm volatile("cp.async.wait_group 0;" ::: "memory");
        }
        __syncthreads();   // chunk c's staging fully visible

        float* stg = sm + ((c & 1) ? K3_STG1 : K3_STG0);
        float* smf = sm + ((c & 1) ? K3_SMF1 : K3_SMF0);
        if (c < 8) {
#pragma unroll
            for (int t = 0; t < 4; t++) {
                int j = jj + 2 * t;
                const float* xj = stg + j * 408 + px;
                float fc = wv[0] * xj[3]       + wv[1] * xj[4]       + wv[2] * xj[5];
                fc      += wv[3] * xj[136 + 3] + wv[4] * xj[136 + 4] + wv[5] * xj[136 + 5];
                fc      += wv[6] * xj[272 + 3] + wv[7] * xj[272 + 4] + wv[8] * xj[272 + 5];
                smf[j * 128 + px] = fc;
            }
        } else {
            float wg = stg[1024 + px];
#pragma unroll
            for (int t = 0; t < 4; t++) {
                int j = jj + 2 * t;
                smf[j * 128 + px] = fmaxf(stg[j * 128 + px] * a2s[j] + b2s[j], 0.f) * wg;
            }
        }
        __syncthreads();   // smf ready

        // GEMM: f per-lane (4 px, dup), w broadcast packed pairs (8 ch = 4 pairs)
#pragma unroll
        for (int kk = 0; kk < 8; kk++) {
            float4 f = *reinterpret_cast<const float4*>(smf + kk * 128 + pg * 4);
            unsigned long long fd0, fd1, fd2, fd3;
            PACK2(fd0, f.x); PACK2(fd1, f.y); PACK2(fd2, f.z); PACK2(fd3, f.w);
            const float* wr = wTs + (c * 8 + kk) * 64 + cg * 8;
            ulonglong2 wp0 = *reinterpret_cast<const ulonglong2*>(wr);
            ulonglong2 wp1 = *reinterpret_cast<const ulonglong2*>(wr + 4);
            unsigned long long wp[4] = {wp0.x, wp0.y, wp1.x, wp1.y};
#pragma unroll
            for (int cp = 0; cp < 4; cp++) {
                FMA2(acc[0 * 4 + cp], fd0, wp[cp]);
                FMA2(acc[1 * 4 + cp], fd1, wp[cp]);
                FMA2(acc[2 * 4 + cp], fd2, wp[cp]);
                FMA2(acc[3 * 4 + cp], fd3, wp[cp]);
            }
        }
    }

    // ---- epilogue: store raw out + abn stats ----
    const float* mp = mask + (size_t)b * HW + p0 + pg * 4;
    float4 mk = *reinterpret_cast<const float4*>(mp);
    float mm[4] = { mk.x > 0.f ? 1.f : 0.f, mk.y > 0.f ? 1.f : 0.f,
                    mk.z > 0.f ? 1.f : 0.f, mk.w > 0.f ? 1.f : 0.f };

    float* ob = out + (size_t)b * 64 * HW + p0 + pg * 4;
    int lane = tid & 31;
#pragma unroll
    for (int cp = 0; cp < 4; cp++) {
        float lo0 = __uint_as_float((unsigned)acc[0 * 4 + cp]);
        float hi0 = __uint_as_float((unsigned)(acc[0 * 4 + cp] >> 32));
        float lo1 = __uint_as_float((unsigned)acc[1 * 4 + cp]);
        float hi1 = __uint_as_float((unsigned)(acc[1 * 4 + cp] >> 32));
        float lo2 = __uint_as_float((unsigned)acc[2 * 4 + cp]);
        float hi2 = __uint_as_float((unsigned)(acc[2 * 4 + cp] >> 32));
        float lo3 = __uint_as_float((unsigned)acc[3 * 4 + cp]);
        float hi3 = __uint_as_float((unsigned)(acc[3 * 4 + cp] >> 32));
        int chE = cg * 8 + 2 * cp;
        float4 vE = make_float4(lo0, lo1, lo2, lo3);
        float4 vO = make_float4(hi0, hi1, hi2, hi3);
        *reinterpret_cast<float4*>(ob + (size_t)chE * HW) = vE;
        *reinterpret_cast<float4*>(ob + (size_t)(chE + 1) * HW) = vO;

        float svE = lo0 * mm[0] + lo1 * mm[1] + lo2 * mm[2] + lo3 * mm[3];
        float qE  = lo0 * lo0 * mm[0] + lo1 * lo1 * mm[1] + lo2 * lo2 * mm[2] + lo3 * lo3 * mm[3];
        float svO = hi0 * mm[0] + hi1 * mm[1] + hi2 * mm[2] + hi3 * mm[3];
        float qO  = hi0 * hi0 * mm[0] + hi1 * hi1 * mm[1] + hi2 * hi2 * mm[2] + hi3 * hi3 * mm[3];
#pragma unroll
        for (int o2 = 16; o2; o2 >>= 1) {
            svE += __shfl_down_sync(0xffffffffu, svE, o2);
            qE  += __shfl_down_sync(0xffffffffu, qE, o2);
            svO += __shfl_down_sync(0xffffffffu, svO, o2);
            qO  += __shfl_down_sync(0xffffffffu, qO, o2);
        }
        if (lane == 0) {
            atomicAdd(&g_acc[32 + 2 * chE], svE);
            atomicAdd(&g_acc[33 + 2 * chE], qE);
            atomicAdd(&g_acc[32 + 2 * (chE + 1)], svO);
            atomicAdd(&g_acc[33 + 2 * (chE + 1)], qO);
        }
    }
}

// ---------------- K4: abn normalize + relu + mask ----------------
__global__ void k4_final(float* __restrict__ out, const float* __restrict__ mask,
                         const float* __restrict__ abn_g, const float* __restrict__ abn_b) {
    int t = blockIdx.x * 256 + threadIdx.x;
    int e = t * 4;
    int b = e >> 22;
    int c = (e >> 16) & 63;
    int p = e & (HW - 1);
    float n0   = fmaxf(g_acc[1], 1.f);
    float mean = g_acc[32 + 2 * c] / n0;
    float var  = g_acc[33 + 2 * c] / n0 - mean * mean;
    float a    = abn_g[c] * rsqrtf(var + 1e-5f);
    float bb   = abn_b[c] - mean * a;
    float4 v  = reinterpret_cast<float4*>(out)[t];
    float4 mk = *reinterpret_cast<const float4*>(mask + (size_t)b * HW + p);
    v.x = (mk.x > 0.f) ? fmaxf(v.x * a + bb, 0.f) : 0.f;
    v.y = (mk.y > 0.f) ? fmaxf(v.y * a + bb, 0.f) : 0.f;
    v.z = (mk.z > 0.f) ? fmaxf(v.z * a + bb, 0.f) : 0.f;
    v.w = (mk.w > 0.f) ? fmaxf(v.w * a + bb, 0.f) : 0.f;
    reinterpret_cast<float4*>(out)[t] = v;
}

// ---------------- host launcher ----------------
extern "C" void kernel_launch(void* const* d_in, const int* in_sizes, int n_in,
                              void* d_out, int out_size) {
    const float* x      = (const float*)d_in[0];
    const float* mask   = (const float*)d_in[1];
    const float* w1     = (const float*)d_in[2];
    const float* bn1_g  = (const float*)d_in[3];
    const float* bn1_b  = (const float*)d_in[4];
    const float* w2     = (const float*)d_in[5];
    const float* b2     = (const float*)d_in[6];
    const float* g1     = (const float*)d_in[7];
    const float* gbn1_g = (const float*)d_in[8];
    const float* gbn1_b = (const float*)d_in[9];
    const float* g2     = (const float*)d_in[10];
    const float* gbn2_g = (const float*)d_in[11];
    const float* gbn2_b = (const float*)d_in[12];
    const float* w_agg  = (const float*)d_in[13];
    const float* abn_g  = (const float*)d_in[14];
    const float* abn_b  = (const float*)d_in[15];
    float* out = (float*)d_out;

    cudaFuncSetAttribute(k3_gemm, cudaFuncAttributeMaxDynamicSharedMemorySize, K3_SMEMF * 4);

    k0_zero<<<1, 256>>>();
    k1_stats<<<BHW / 256, 256>>>(x, mask);
    k2_wts<<<BHW / 256, 256>>>(x, mask, w1, bn1_g, bn1_b, w2, b2, g1, gbn1_g, gbn1_b, g2);
    k3_gemm<<<BHW / 128, 256, K3_SMEMF * 4>>>(x, mask, w_agg, gbn2_g, gbn2_b, out);
    k4_final<<<(2 * 64 * HW / 4) / 256, 256>>>(out, mask, abn_g, abn_b);
}

// round 13
// speedup vs baseline: 1.0393x; 1.0090x over previous
#include <cuda_runtime.h>
#include <cstdint>

#define HW     65536
#define BHW    131072
#define WDIM   1024
#define HDIM   64

// ---------------- global scratch ----------------
// g_acc: [0]=N1 (masked (p,k) count)  [1]=N0 (mp0 count)
// [2..5] Sum pn_a   [6..15] Sum pn_a*pn_b (a<=b: 00,01,02,03,11,12,13,22,23,33)
// [16..23] SG2  [24..31] QG2
// [32..159] interleaved: [32+2c]=SA_c [33+2c]=QA_c
__device__ float g_acc[160];
__device__ float g_wT[136 * 64];    // transposed w_agg: g_wT[k][o]
__device__ float g_wts[9 * BHW];    // softmax weights (full), plane-major
__device__ float g_wtsg[9 * BHW];   // msel-masked softmax weights
__device__ float g_vv[72 * BHW];    // pre-BN2 g values, plane-major [k*8+j]

#define PACK2(dst, f) asm("mov.b64 %0, {%1, %1};" : "=l"(dst) : "r"(__float_as_uint(f)))
#define FMA2(acc, a, b) asm("fma.rn.f32x2 %0, %1, %2, %0;" : "+l"(acc) : "l"(a), "l"(b))

__device__ __forceinline__ uint32_t smem_u32(const void* p) {
    uint32_t a;
    asm("{ .reg .u64 t; cvta.to.shared.u64 t, %1; cvt.u32.u64 %0, t; }" : "=r"(a) : "l"(p));
    return a;
}

// ---------------- block reduction -> atomicAdd into g_acc ----------------
template <int NV, int NW>
__device__ __forceinline__ void block_reduce_atomic(const float* vals, float* red, int tid, int accBase) {
    int lane = tid & 31, w = tid >> 5;
#pragma unroll
    for (int v = 0; v < NV; v++) {
        float r = vals[v];
#pragma unroll
        for (int o = 16; o; o >>= 1) r += __shfl_down_sync(0xffffffffu, r, o);
        if (lane == 0) red[v * NW + w] = r;
    }
    __syncthreads();
    if (tid < NV) {
        float r = 0.f;
#pragma unroll
        for (int ww = 0; ww < NW; ww++) r += red[tid * NW + ww];
        atomicAdd(&g_acc[accBase + tid], r);
    }
}

// first-layer BN affine from pn moments: var(w.pn) = w^T Cov w
__device__ __forceinline__ void affine_from_moments(const float* wrow, float gam, float bet,
                                                    float& a_out, float& b_out) {
    float n = fmaxf(g_acc[0], 1.f);
    const int qi[4][4] = {{0,1,2,3},{1,4,5,6},{2,5,7,8},{3,6,8,9}};
    float e2 = 0.f, mean = 0.f;
#pragma unroll
    for (int a = 0; a < 4; a++) {
        float wa = wrow[a];
        mean += wa * (g_acc[2 + a] / n);
        float row = 0.f;
#pragma unroll
        for (int bb = 0; bb < 4; bb++) row += wrow[bb] * (g_acc[6 + qi[a][bb]] / n);
        e2 += wa * row;
    }
    float var = e2 - mean * mean;
    float a_ = gam * rsqrtf(var + 1e-5f);
    a_out = a_;
    b_out = bet - mean * a_;
}

// ---------------- K0: zero accumulators + transpose w_agg ----------------
__global__ void k0_zero(const float* __restrict__ w_agg) {
    int t = threadIdx.x;
    if (t < 160) g_acc[t] = 0.f;
    for (int e = t; e < 136 * 64; e += 256) {
        int o = e & 63, k = e >> 6;
        g_wT[e] = w_agg[o * 136 + k];
    }
}

// ---------------- K1: pn moment stats + mask counts (tiled) ----------------
__global__ void k1_stats(const float* __restrict__ x, const float* __restrict__ mask) {
    __shared__ float tile[5 * 3 * 260];
    __shared__ float red[16 * 8];
    int tid = threadIdx.x;

    int base = blockIdx.x * 256;
    int b = base >> 16, p0 = base & (HW - 1);
    int y = p0 >> 10, x0 = p0 & (WDIM - 1);
    const float* xb0 = x + (size_t)b * 68 * HW;
    const float* mb = mask + (size_t)b * HW;

    for (int f = tid; f < 5 * 3 * 260; f += 256) {
        int pl = f / 780, rem = f - pl * 780;
        int r = rem / 260, cx = rem - r * 260;
        float v = 0.f;
        if (cx < 258) {
            int gy = y - 1 + r, gx = x0 - 1 + cx;
            if (gy >= 0 && gy < HDIM && gx >= 0 && gx < WDIM) {
                int gp = gy * WDIM + gx;
                v = (pl == 0) ? mb[gp] : xb0[(size_t)(pl - 1) * HW + gp];
            }
        }
        tile[f] = v;
    }
    __syncthreads();

    int cc = tid + 1;
    float c0 = tile[780 + 260 + cc], c1 = tile[2 * 780 + 260 + cc];
    float c2 = tile[3 * 780 + 260 + cc], c3 = tile[4 * 780 + 260 + cc];
    float cnt1 = 0.f, cnt0 = (tile[260 + cc] > 0.f) ? 1.f : 0.f;
    float s[4] = {0.f, 0.f, 0.f, 0.f};
    float q[10];
#pragma unroll
    for (int j = 0; j < 10; j++) q[j] = 0.f;

#pragma unroll
    for (int k = 0; k < 9; k++) {
        int r = k / 3, dx = k % 3 - 1;
        int tix = r * 260 + cc + dx;
        if (!(tile[tix] > 0.f)) continue;
        cnt1 += 1.f;
        float pn0 = tile[780 + tix] - c0, pn1 = tile[2 * 780 + tix] - c1;
        float pn2 = tile[3 * 780 + tix] - c2, pn3 = tile[4 * 780 + tix] - c3;
        s[0] += pn0; s[1] += pn1; s[2] += pn2; s[3] += pn3;
        q[0] += pn0 * pn0; q[1] += pn0 * pn1; q[2] += pn0 * pn2; q[3] += pn0 * pn3;
        q[4] += pn1 * pn1; q[5] += pn1 * pn2; q[6] += pn1 * pn3;
        q[7] += pn2 * pn2; q[8] += pn2 * pn3; q[9] += pn3 * pn3;
    }

    float vals[16];
    vals[0] = cnt1; vals[1] = cnt0;
#pragma unroll
    for (int a = 0; a < 4; a++) vals[2 + a] = s[a];
#pragma unroll
    for (int j = 0; j < 10; j++) vals[6 + j] = q[j];
    block_reduce_atomic<16, 8>(vals, red, tid, 0);
}

// ---------------- K2: softmax weights + vv planes + gbn2 stats ----------------
__global__ void k2_wts(const float* __restrict__ x, const float* __restrict__ mask,
                       const float* __restrict__ w1, const float* __restrict__ bn1_g,
                       const float* __restrict__ bn1_b, const float* __restrict__ w2,
                       const float* __restrict__ b2, const float* __restrict__ g1,
                       const float* __restrict__ gbn1_g, const float* __restrict__ gbn1_b,
                       const float* __restrict__ g2) {
    __shared__ float tile[5 * 3 * 260];
    __shared__ float w1s[32], g1s[32], g2s[64], w2s[8], abp[32], b2sh[1];
    __shared__ float red[16 * 8];
    int tid = threadIdx.x;
    if (tid < 32) { w1s[tid] = w1[tid]; g1s[tid] = g1[tid]; }
    if (tid < 64) g2s[tid] = g2[tid];
    if (tid < 8)  w2s[tid] = w2[tid];
    if (tid == 0) b2sh[0] = b2[0];
    if (tid >= 64 && tid < 80) {
        int t2 = tid - 64;
        int path = t2 >> 3, j = t2 & 7;
        const float* wrow = (path ? g1 : w1) + j * 4;
        float gam = path ? gbn1_g[j] : bn1_g[j];
        float bet = path ? gbn1_b[j] : bn1_b[j];
        float a_, b_;
        affine_from_moments(wrow, gam, bet, a_, b_);
        abp[path * 16 + j] = a_;
        abp[path * 16 + 8 + j] = b_;
    }

    int base = blockIdx.x * 256;
    int b = base >> 16, p0 = base & (HW - 1);
    int y = p0 >> 10, x0 = p0 & (WDIM - 1);
    const float* xb0 = x + (size_t)b * 68 * HW;
    const float* mb = mask + (size_t)b * HW;

    for (int f = tid; f < 5 * 3 * 260; f += 256) {
        int pl = f / 780, rem = f - pl * 780;
        int r = rem / 260, cx = rem - r * 260;
        float v = 0.f;
        if (cx < 258) {
            int gy = y - 1 + r, gx = x0 - 1 + cx;
            if (gy >= 0 && gy < HDIM && gx >= 0 && gx < WDIM) {
                int gp = gy * WDIM + gx;
                v = (pl == 0) ? mb[gp] : xb0[(size_t)(pl - 1) * HW + gp];
            }
        }
        tile[f] = v;
    }
    __syncthreads();

    int i = base + tid;
    int cc = tid + 1;
    float c0 = tile[780 + 260 + cc], c1 = tile[2 * 780 + 260 + cc];
    float c2 = tile[3 * 780 + 260 + cc], c3 = tile[4 * 780 + 260 + cc];
    float logit[9];
    float sg2[8], qg2[8];
#pragma unroll
    for (int j = 0; j < 8; j++) { sg2[j] = qg2[j] = 0.f; }
    unsigned mbits = 0;

#pragma unroll
    for (int k = 0; k < 9; k++) {
        int r = k / 3, dx = k % 3 - 1;
        int tix = r * 260 + cc + dx;
        float lg = 0.f;
        if (tile[tix] > 0.f) {
            mbits |= 1u << k;
            float pn0 = tile[780 + tix] - c0, pn1 = tile[2 * 780 + tix] - c1;
            float pn2 = tile[3 * 780 + tix] - c2, pn3 = tile[4 * 780 + tix] - c3;
            float u[8];
            float l = b2sh[0];
#pragma unroll
            for (int j = 0; j < 8; j++) {
                float h = pn0 * w1s[j * 4] + pn1 * w1s[j * 4 + 1] + pn2 * w1s[j * 4 + 2] + pn3 * w1s[j * 4 + 3];
                float hn = fmaxf(h * abp[j] + abp[8 + j], 0.f);
                l += hn * w2s[j];
                float qv = pn0 * g1s[j * 4] + pn1 * g1s[j * 4 + 1] + pn2 * g1s[j * 4 + 2] + pn3 * g1s[j * 4 + 3];
                u[j] = fmaxf(qv * abp[16 + j] + abp[24 + j], 0.f);
            }
            lg = l;
#pragma unroll
            for (int j = 0; j < 8; j++) {
                float vv = 0.f;
#pragma unroll
                for (int m = 0; m < 8; m++) vv += u[m] * g2s[j * 8 + m];
                g_vv[(size_t)(k * 8 + j) * BHW + i] = vv;
                sg2[j] += vv; qg2[j] += vv * vv;
            }
        } else {
#pragma unroll
            for (int j = 0; j < 8; j++) g_vv[(size_t)(k * 8 + j) * BHW + i] = 0.f;
        }
        logit[k] = lg;
    }

    float mx = logit[0];
#pragma unroll
    for (int k = 1; k < 9; k++) mx = fmaxf(mx, logit[k]);
    float s = 0.f, e[9];
#pragma unroll
    for (int k = 0; k < 9; k++) { e[k] = __expf(logit[k] - mx); s += e[k]; }
    float inv = 1.f / s;
#pragma unroll
    for (int k = 0; k < 9; k++) {
        float wk = e[k] * inv;
        g_wts[(size_t)k * BHW + i] = wk;
        g_wtsg[(size_t)k * BHW + i] = ((mbits >> k) & 1u) ? wk : 0.f;
    }

    float vals[16];
#pragma unroll
    for (int j = 0; j < 8; j++) { vals[j] = sg2[j]; vals[8 + j] = qg2[j]; }
    block_reduce_atomic<16, 8>(vals, red, tid, 16);
}

// ---------------- K3: fused producer+GEMM, streamed weights, 4 blocks/SM ----------------
// dynamic smem (floats):
//   stg0 [0, 3776)      staging A: fagg [8][3][136]=3264 (or g: vv[8][128]+wg[128]); w chunk [3264,3776)
//   stg1 [3776, 7552)   staging B (same layout)
//   smf0 [7552, 8576)   feats chunk A [8][128]
//   smf1 [8576, 9600)   feats chunk B
#define K3_STGSZ 3776
#define K3_WOFF  3264
#define K3_SMF0  7552
#define K3_SMF1  8576
#define K3_SMEMF 9600

__device__ __forceinline__ void k3_issue_fagg(uint32_t stg, const float* __restrict__ xpl,
                                              int y, int x0, int tid) {
#pragma unroll
    for (int q = 0; q < 3; q++) {
        int s = q * 256 + tid;              // 0..767
        int j = s / 96;
        int rem = s - j * 96;
        int r = rem >> 5, c4 = rem & 31;
        int gy = y - 1 + r;
        int ok = (gy >= 0 && gy < HDIM) ? 16 : 0;
        int gyc = min(max(gy, 0), HDIM - 1);
        const float* src = xpl + (size_t)j * HW + gyc * WDIM + x0 + 4 * c4;
        uint32_t dst = stg + (uint32_t)(j * 408 + r * 136 + 4 + 4 * c4) * 4u;
        asm volatile("cp.async.cg.shared.global [%0], [%1], 16, %2;" :: "r"(dst), "l"(src), "r"(ok) : "memory");
    }
    if (tid < 48) {
        int j = tid / 6, rem = tid % 6;
        int r = rem >> 1, side = rem & 1;
        int gy = y - 1 + r;
        int gx = side ? x0 + 128 : x0 - 1;
        int ok = (gy >= 0 && gy < HDIM && gx >= 0 && gx < WDIM) ? 4 : 0;
        int gyc = min(max(gy, 0), HDIM - 1);
        int gxc = min(max(gx, 0), WDIM - 1);
        const float* src = xpl + (size_t)j * HW + gyc * WDIM + gxc;
        uint32_t dst = stg + (uint32_t)(j * 408 + r * 136 + (side ? 132 : 3)) * 4u;
        asm volatile("cp.async.ca.shared.global [%0], [%1], 4, %2;" :: "r"(dst), "l"(src), "r"(ok) : "memory");
    }
}

__device__ __forceinline__ void k3_issue_g(uint32_t stg, const float* __restrict__ vvb,
                                           const float* __restrict__ wgb, int tid) {
    {   // vv: [8][128] = 256 x 16B
        int j = tid >> 5, c4 = tid & 31;
        const float* src = vvb + (size_t)j * BHW + 4 * c4;
        uint32_t dst = stg + (uint32_t)(j * 128 + 4 * c4) * 4u;
        asm volatile("cp.async.cg.shared.global [%0], [%1], 16;" :: "r"(dst), "l"(src) : "memory");
    }
    if (tid < 32) {   // wg: 128 floats = 32 x 16B
        const float* src = wgb + 4 * tid;
        uint32_t dst = stg + (uint32_t)(1024 + 4 * tid) * 4u;
        asm volatile("cp.async.cg.shared.global [%0], [%1], 16;" :: "r"(dst), "l"(src) : "memory");
    }
}

__device__ __forceinline__ void k3_issue_w(uint32_t stg, const float* __restrict__ wsrc, int tid) {
    if (tid < 128) {   // 512 floats = 128 x 16B
        uint32_t dst = stg + (uint32_t)(K3_WOFF + 4 * tid) * 4u;
        asm volatile("cp.async.ca.shared.global [%0], [%1], 16;" :: "r"(dst), "l"(wsrc + 4 * tid) : "memory");
    }
}

__global__ void __launch_bounds__(256, 4) k3_gemm(const float* __restrict__ x,
                                                  const float* __restrict__ mask,
                                                  const float* __restrict__ gbn2_g,
                                                  const float* __restrict__ gbn2_b,
                                                  float* __restrict__ out) {
    extern __shared__ float sm[];
    __shared__ float a2s[8], b2s[8];
    int tid = threadIdx.x;
    uint32_t smb = smem_u32(sm);
    uint32_t stgu0 = smb, stgu1 = smb + K3_STGSZ * 4u;

    if (tid < 8) {
        float n = fmaxf(g_acc[0], 1.f);
        float mean2 = g_acc[16 + tid] / n;
        float var2  = g_acc[24 + tid] / n - mean2 * mean2;
        float a2 = gbn2_g[tid] * rsqrtf(var2 + 1e-5f);
        a2s[tid] = a2;
        b2s[tid] = gbn2_b[tid] - mean2 * a2;
    }

    int base = blockIdx.x * 128;
    int b = base >> 16, p0 = base & (HW - 1);
    int y = p0 >> 10, x0 = p0 & (WDIM - 1);
    const float* xb4 = x + (size_t)b * 68 * HW + (size_t)4 * HW;

    int px = tid & 127, jj = tid >> 7;     // transform mapping: 2 threads per px
    int lane = tid & 31;
    float wv[9];
#pragma unroll
    for (int k = 0; k < 9; k++) wv[k] = g_wts[(size_t)k * BHW + base + px];

    // prologue: issue chunk 0 (fagg channels 0..7) + w chunk 0
    k3_issue_fagg(stgu0, xb4, y, x0, tid);
    k3_issue_w(stgu0, g_wT, tid);
    asm volatile("cp.async.commit_group;" ::: "memory");

    // GEMM tiling: 4 px x 8 ch per thread (pg 0..31 -> px pg*4; cg 0..7 -> ch cg*8)
    int pg = tid & 31, cg = tid >> 5;
    unsigned long long acc[16];
#pragma unroll
    for (int t = 0; t < 16; t++) acc[t] = 0ULL;

    for (int c = 0; c < 17; c++) {
        if (c < 16) {
            int cn = c + 1;
            uint32_t stgn = (cn & 1) ? stgu1 : stgu0;
            if (cn < 8) {
                k3_issue_fagg(stgn, xb4 + (size_t)(8 * cn) * HW, y, x0, tid);
            } else {
                int k = cn - 8;
                k3_issue_g(stgn, g_vv + (size_t)(k * 8) * BHW + base,
                           g_wtsg + (size_t)k * BHW + base, tid);
            }
            k3_issue_w(stgn, g_wT + cn * 512, tid);
            asm volatile("cp.async.commit_group;" ::: "memory");
            asm volatile("cp.async.wait_group 1;" ::: "memory");
        } else {
            asm volatile("cp.async.wait_group 0;" ::: "memory");
        }
        __syncthreads();   // chunk c's staging fully visible

        float* stg = sm + ((c & 1) ? K3_STGSZ : 0);
        float* smf = sm + ((c & 1) ? K3_SMF1 : K3_SMF0);
        if (c < 8) {
            // shuffle-based 3x3 stencil: 1 LDS + 2 SHFL per row (+ edge lanes)
#pragma unroll
            for (int t = 0; t < 4; t++) {
                int j = jj + 2 * t;
                const float* xj = stg + j * 408;
                float fc = 0.f;
#pragma unroll
                for (int r = 0; r < 3; r++) {
                    const float* row = xj + r * 136;
                    float m = row[4 + px];
                    float lf = __shfl_up_sync(0xffffffffu, m, 1);
                    if (lane == 0) lf = row[3 + px];
                    float rt = __shfl_down_sync(0xffffffffu, m, 1);
                    if (lane == 31) rt = row[5 + px];
                    fc += wv[r * 3] * lf + wv[r * 3 + 1] * m + wv[r * 3 + 2] * rt;
                }
                smf[j * 128 + px] = fc;
            }
        } else {
            float wg = stg[1024 + px];
#pragma unroll
            for (int t = 0; t < 4; t++) {
                int j = jj + 2 * t;
                smf[j * 128 + px] = fmaxf(stg[j * 128 + px] * a2s[j] + b2s[j], 0.f) * wg;
            }
        }
        __syncthreads();   // smf ready

        // GEMM: f per-lane (4 px, dup), w broadcast packed pairs from streamed chunk
        const float* wch = stg + K3_WOFF;
#pragma unroll
        for (int kk = 0; kk < 8; kk++) {
            float4 f = *reinterpret_cast<const float4*>(smf + kk * 128 + pg * 4);
            unsigned long long fd0, fd1, fd2, fd3;
            PACK2(fd0, f.x); PACK2(fd1, f.y); PACK2(fd2, f.z); PACK2(fd3, f.w);
            const float* wr = wch + kk * 64 + cg * 8;
            ulonglong2 wp0 = *reinterpret_cast<const ulonglong2*>(wr);
            ulonglong2 wp1 = *reinterpret_cast<const ulonglong2*>(wr + 4);
            unsigned long long wp[4] = {wp0.x, wp0.y, wp1.x, wp1.y};
#pragma unroll
            for (int cp = 0; cp < 4; cp++) {
                FMA2(acc[0 * 4 + cp], fd0, wp[cp]);
                FMA2(acc[1 * 4 + cp], fd1, wp[cp]);
                FMA2(acc[2 * 4 + cp], fd2, wp[cp]);
                FMA2(acc[3 * 4 + cp], fd3, wp[cp]);
            }
        }
        // trailing barrier: the GEMM reads wch (in stg buffer c&1); chunk c+2's
        // cp.async (issued at top of iteration c+1) writes that same buffer.
        // Without this barrier a fast warp's issue could race a slow warp's reads.
        __syncthreads();
    }

    // ---- epilogue: store raw out + abn stats ----
    const float* mp = mask + (size_t)b * HW + p0 + pg * 4;
    float4 mk = *reinterpret_cast<const float4*>(mp);
    float mm[4] = { mk.x > 0.f ? 1.f : 0.f, mk.y > 0.f ? 1.f : 0.f,
                    mk.z > 0.f ? 1.f : 0.f, mk.w > 0.f ? 1.f : 0.f };

    float* ob = out + (size_t)b * 64 * HW + p0 + pg * 4;
#pragma unroll
    for (int cp = 0; cp < 4; cp++) {
        float lo0 = __uint_as_float((unsigned)acc[0 * 4 + cp]);
        float hi0 = __uint_as_float((unsigned)(acc[0 * 4 + cp] >> 32));
        float lo1 = __uint_as_float((unsigned)acc[1 * 4 + cp]);
        float hi1 = __uint_as_float((unsigned)(acc[1 * 4 + cp] >> 32));
        float lo2 = __uint_as_float((unsigned)acc[2 * 4 + cp]);
        float hi2 = __uint_as_float((unsigned)(acc[2 * 4 + cp] >> 32));
        float lo3 = __uint_as_float((unsigned)acc[3 * 4 + cp]);
        float hi3 = __uint_as_float((unsigned)(acc[3 * 4 + cp] >> 32));
        int chE = cg * 8 + 2 * cp;
        float4 vE = make_float4(lo0, lo1, lo2, lo3);
        float4 vO = make_float4(hi0, hi1, hi2, hi3);
        *reinterpret_cast<float4*>(ob + (size_t)chE * HW) = vE;
        *reinterpret_cast<float4*>(ob + (size_t)(chE + 1) * HW) = vO;

        float svE = lo0 * mm[0] + lo1 * mm[1] + lo2 * mm[2] + lo3 * mm[3];
        float qE  = lo0 * lo0 * mm[0] + lo1 * lo1 * mm[1] + lo2 * lo2 * mm[2] + lo3 * lo3 * mm[3];
        float svO = hi0 * mm[0] + hi1 * mm[1] + hi2 * mm[2] + hi3 * mm[3];
        float qO  = hi0 * hi0 * mm[0] + hi1 * hi1 * mm[1] + hi2 * hi2 * mm[2] + hi3 * hi3 * mm[3];
#pragma unroll
        for (int o2 = 16; o2; o2 >>= 1) {
            svE += __shfl_down_sync(0xffffffffu, svE, o2);
            qE  += __shfl_down_sync(0xffffffffu, qE, o2);
            svO += __shfl_down_sync(0xffffffffu, svO, o2);
            qO  += __shfl_down_sync(0xffffffffu, qO, o2);
        }
        if (lane == 0) {
            atomicAdd(&g_acc[32 + 2 * chE], svE);
            atomicAdd(&g_acc[33 + 2 * chE], qE);
            atomicAdd(&g_acc[32 + 2 * (chE + 1)], svO);
            atomicAdd(&g_acc[33 + 2 * (chE + 1)], qO);
        }
    }
}

// ---------------- K4: abn normalize + relu + mask ----------------
__global__ void k4_final(float* __restrict__ out, const float* __restrict__ mask,
                         const float* __restrict__ abn_g, const float* __restrict__ abn_b) {
    int t = blockIdx.x * 256 + threadIdx.x;
    int e = t * 4;
    int b = e >> 22;
    int c = (e >> 16) & 63;
    int p = e & (HW - 1);
    float n0   = fmaxf(g_acc[1], 1.f);
    float mean = g_acc[32 + 2 * c] / n0;
    float var  = g_acc[33 + 2 * c] / n0 - mean * mean;
    float a    = abn_g[c] * rsqrtf(var + 1e-5f);
    float bb   = abn_b[c] - mean * a;
    float4 v  = reinterpret_cast<float4*>(out)[t];
    float4 mk = *reinterpret_cast<const float4*>(mask + (size_t)b * HW + p);
    v.x = (mk.x > 0.f) ? fmaxf(v.x * a + bb, 0.f) : 0.f;
    v.y = (mk.y > 0.f) ? fmaxf(v.y * a + bb, 0.f) : 0.f;
    v.z = (mk.z > 0.f) ? fmaxf(v.z * a + bb, 0.f) : 0.f;
    v.w = (mk.w > 0.f) ? fmaxf(v.w * a + bb, 0.f) : 0.f;
    reinterpret_cast<float4*>(out)[t] = v;
}

// ---------------- host launcher ----------------
extern "C" void kernel_launch(void* const* d_in, const int* in_sizes, int n_in,
                              void* d_out, int out_size) {
    const float* x      = (const float*)d_in[0];
    const float* mask   = (const float*)d_in[1];
    const float* w1     = (const float*)d_in[2];
    const float* bn1_g  = (const float*)d_in[3];
    const float* bn1_b  = (const float*)d_in[4];
    const float* w2     = (const float*)d_in[5];
    const float* b2     = (const float*)d_in[6];
    const float* g1     = (const float*)d_in[7];
    const float* gbn1_g = (const float*)d_in[8];
    const float* gbn1_b = (const float*)d_in[9];
    const float* g2     = (const float*)d_in[10];
    const float* gbn2_g = (const float*)d_in[11];
    const float* gbn2_b = (const float*)d_in[12];
    const float* w_agg  = (const float*)d_in[13];
    const float* abn_g  = (const float*)d_in[14];
    const float* abn_b  = (const float*)d_in[15];
    float* out = (float*)d_out;

    cudaFuncSetAttribute(k3_gemm, cudaFuncAttributeMaxDynamicSharedMemorySize, K3_SMEMF * 4);

    k0_zero<<<1, 256>>>(w_agg);
    k1_stats<<<BHW / 256, 256>>>(x, mask);
    k2_wts<<<BHW / 256, 256>>>(x, mask, w1, bn1_g, bn1_b, w2, b2, g1, gbn1_g, gbn1_b, g2);
    k3_gemm<<<BHW / 128, 256, K3_SMEMF * 4>>>(x, mask, gbn2_g, gbn2_b, out);
    k4_final<<<(2 * 64 * HW / 4) / 256, 256>>>(out, mask, abn_g, abn_b);
}